// round 6
// baseline (speedup 1.0000x reference)
#include <cuda_runtime.h>
#include <cuda_bf16.h>
#include <cstdint>
#include <cstddef>

#define Bn 8
#define Tn 2048
#define Dn 128

typedef unsigned long long ull;

// ---- scratch (static device globals; no allocations) ----
__device__ __nv_bfloat16 g_zbf[Bn * Tn * Dn];   // 4 MB
__device__ float        g_z2[Bn * Tn];          // 64 KB
__device__ double       g_part[Bn * 16 * 8];    // 1024 partials

__device__ __forceinline__ uint32_t smem_u32(const void* p) {
    uint32_t a;
    asm("{ .reg .u64 t; cvta.to.shared.u64 t, %1; cvt.u32.u64 %0, t; }"
        : "=r"(a) : "l"(p));
    return a;
}

// ---- packed f32x2 helpers ----
#define MUL2(o, a, b)    asm("mul.rn.f32x2 %0, %1, %2;" : "=l"(o) : "l"(a), "l"(b))
#define ADD2(o, a, b)    asm("add.rn.f32x2 %0, %1, %2;" : "=l"(o) : "l"(a), "l"(b))
#define FMA2(o, a, b, c) asm("fma.rn.f32x2 %0, %1, %2, %3;" : "=l"(o) : "l"(a), "l"(b), "l"(c))
#define PACK2(o, lo, hi) asm("mov.b64 %0, {%1, %2};" : "=l"(o) : "f"(lo), "f"(hi))
#define UNPK2(lo, hi, v) asm("mov.b64 {%0, %1}, %2;" : "=f"(lo), "=f"(hi) : "l"(v))
#define EX2F(d, a)       asm("ex2.approx.ftz.f32 %0, %1;" : "=f"(d) : "f"(a))

#define LDSM_X4(r0, r1, r2, r3, a) \
    asm volatile("ldmatrix.sync.aligned.m8n8.x4.shared.b16 {%0,%1,%2,%3}, [%4];" \
                 : "=r"(r0), "=r"(r1), "=r"(r2), "=r"(r3) : "r"(a))

// ============================================================
// Kernel 1: bf16 cast of z + per-row squared norms (4 rows/warp)
// ============================================================
__global__ void __launch_bounds__(256) prep_kernel(const float* __restrict__ z) {
    const int warp = threadIdx.x >> 5, lane = threadIdx.x & 31;
    const int row0 = blockIdx.x * 32 + warp * 4;
    float4 v[4];
    #pragma unroll
    for (int r = 0; r < 4; r++)
        v[r] = ((const float4*)(z + (size_t)(row0 + r) * Dn))[lane];

    #pragma unroll
    for (int r = 0; r < 4; r++) {
        __nv_bfloat162 p0 = __floats2bfloat162_rn(v[r].x, v[r].y);
        __nv_bfloat162 p1 = __floats2bfloat162_rn(v[r].z, v[r].w);
        uint2 o;
        o.x = *reinterpret_cast<uint32_t*>(&p0);
        o.y = *reinterpret_cast<uint32_t*>(&p1);
        ((uint2*)g_zbf)[(size_t)(row0 + r) * 32 + lane] = o;
    }

    float s[4];
    #pragma unroll
    for (int r = 0; r < 4; r++)
        s[r] = v[r].x * v[r].x + v[r].y * v[r].y + v[r].z * v[r].z + v[r].w * v[r].w;
    #pragma unroll
    for (int off = 16; off; off >>= 1) {
        #pragma unroll
        for (int r = 0; r < 4; r++)
            s[r] += __shfl_xor_sync(0xffffffffu, s[r], off);
    }
    if (lane == 0) {
        #pragma unroll
        for (int r = 0; r < 4; r++) g_z2[row0 + r] = s[r];
    }
}

// ============================================================
// Kernel 2: fused 2-tile Gram(MMA) + w + weighted reduction
// grid = (8, 16, 8) = (jt-pair, it, b); 256 threads (8 warps, 4x2)
// smem: zi + zj0 + zj1 (each 128 x 68 words) + z2 rows
// ============================================================
#define SM_WSTRIDE 68
#define TILE_WORDS (128 * SM_WSTRIDE)
#define SMEM_BYTES (3 * TILE_WORDS * 4 + 3 * 128 * 4)

extern __shared__ unsigned char smem_raw[];

__device__ __forceinline__ void gram_mma(uint32_t aAddr0, uint32_t aAddr1,
                                         uint32_t bAddr, float (&acc)[2][8][4]) {
    const uint32_t FN_STRIDE = 16 * SM_WSTRIDE * 4;
    #pragma unroll
    for (int fm = 0; fm < 2; fm++)
        #pragma unroll
        for (int fn = 0; fn < 8; fn++)
            #pragma unroll
            for (int v = 0; v < 4; v++) acc[fm][fn][v] = 0.f;

    #pragma unroll
    for (int ks = 0; ks < 8; ks++) {
        const uint32_t ko = ks * 32;
        uint32_t a[2][4], bb[4][4];
        LDSM_X4(a[0][0], a[0][1], a[0][2], a[0][3], aAddr0 + ko);
        LDSM_X4(a[1][0], a[1][1], a[1][2], a[1][3], aAddr1 + ko);
        #pragma unroll
        for (int p = 0; p < 4; p++)
            LDSM_X4(bb[p][0], bb[p][1], bb[p][2], bb[p][3], bAddr + p * FN_STRIDE + ko);

        #pragma unroll
        for (int p = 0; p < 4; p++) {
            #pragma unroll
            for (int s = 0; s < 2; s++) {
                const int fn = 2 * p + s;
                const uint32_t b0 = bb[p][2 * s], b1 = bb[p][2 * s + 1];
                #pragma unroll
                for (int fm = 0; fm < 2; fm++) {
                    asm volatile(
                        "mma.sync.aligned.m16n8k16.row.col.f32.bf16.bf16.f32 "
                        "{%0,%1,%2,%3}, {%4,%5,%6,%7}, {%8,%9}, {%0,%1,%2,%3};"
                        : "+f"(acc[fm][fn][0]), "+f"(acc[fm][fn][1]),
                          "+f"(acc[fm][fn][2]), "+f"(acc[fm][fn][3])
                        : "r"(a[fm][0]), "r"(a[fm][1]), "r"(a[fm][2]), "r"(a[fm][3]),
                          "r"(b0), "r"(b1));
                }
            }
        }
    }
}

__device__ __forceinline__ float epi_tile(
    const float* __restrict__ gt, int b, int i0, int j0,
    const float* __restrict__ z2i_s, const float* __restrict__ z2j_s,
    int rowBase, int colBase, int gr, int q,
    const float (&acc)[2][8][4], ull CC)
{
    ull zjp[8];
    #pragma unroll
    for (int fn = 0; fn < 8; fn++)
        zjp[fn] = *(const ull*)(z2j_s + colBase + fn * 8 + 2 * q);

    ull szj = 0ull, sacc = 0ull, rw[2][2] = {{0ull, 0ull}, {0ull, 0ull}};

    #pragma unroll
    for (int fm = 0; fm < 2; fm++) {
        const int ri = rowBase + fm * 16 + gr;
        const size_t base0 = (size_t)(b * Tn + i0 + ri) * Tn + j0;   // j-pair units
        const ulonglong2* gA = (const ulonglong2*)gt + (base0 >> 1);
        const ulonglong2* gB = gA + (size_t)(4 * Tn);                // +8 rows
        #pragma unroll
        for (int fn = 0; fn < 8; fn++) {
            const int jh = (colBase + fn * 8 + 2 * q) >> 1;
            const ulonglong2 uA = gA[jh];
            const ulonglong2 uB = gB[jh];
            ull a2, b2; float l0, h0, l1, h1, w0, w1;
            // row A
            MUL2(a2, uA.x, uA.x); MUL2(a2, a2, CC); UNPK2(l0, h0, a2);
            MUL2(b2, uA.y, uA.y); MUL2(b2, b2, CC); UNPK2(l1, h1, b2);
            EX2F(w0, l0 + h0); EX2F(w1, l1 + h1);
            ull wA; PACK2(wA, w0, w1);
            ADD2(rw[fm][0], rw[fm][0], wA);
            FMA2(szj, wA, zjp[fn], szj);
            ull apA; PACK2(apA, acc[fm][fn][0], acc[fm][fn][1]);
            FMA2(sacc, wA, apA, sacc);
            // row B (ri + 8)
            MUL2(a2, uB.x, uB.x); MUL2(a2, a2, CC); UNPK2(l0, h0, a2);
            MUL2(b2, uB.y, uB.y); MUL2(b2, b2, CC); UNPK2(l1, h1, b2);
            EX2F(w0, l0 + h0); EX2F(w1, l1 + h1);
            ull wB; PACK2(wB, w0, w1);
            ADD2(rw[fm][1], rw[fm][1], wB);
            FMA2(szj, wB, zjp[fn], szj);
            ull apB; PACK2(apB, acc[fm][fn][2], acc[fm][fn][3]);
            FMA2(sacc, wB, apB, sacc);
        }
    }

    float s, lo, hi;
    UNPK2(lo, hi, szj);  s  = lo + hi;
    UNPK2(lo, hi, sacc); s -= 2.f * (lo + hi);
    #pragma unroll
    for (int fm = 0; fm < 2; fm++) {
        const int ri = rowBase + fm * 16 + gr;
        UNPK2(lo, hi, rw[fm][0]); s += z2i_s[ri]     * (lo + hi);
        UNPK2(lo, hi, rw[fm][1]); s += z2i_s[ri + 8] * (lo + hi);
    }
    return s;
}

__global__ void __launch_bounds__(256, 2)
main_kernel(const float* __restrict__ gt, const float* __restrict__ sigma) {
    uint32_t* zi  = (uint32_t*)smem_raw;
    uint32_t* zj0 = zi + TILE_WORDS;
    uint32_t* zj1 = zj0 + TILE_WORDS;
    float* z2i_s  = (float*)(zj1 + TILE_WORDS);
    float* z2j0_s = z2i_s + 128;
    float* z2j1_s = z2j0_s + 128;

    const int jt2 = blockIdx.x, it = blockIdx.y, b = blockIdx.z;
    const int i0 = it * 128;
    const int j0a = jt2 * 256, j0b = j0a + 128;
    const int tid = threadIdx.x;
    const int warp = tid >> 5, lane = tid & 31;

    // ---- L2 prefetch of BOTH gt tiles (256KB) ----
    {
        const char* gb = (const char*)gt;
        #pragma unroll
        for (int p = 0; p < 8; p++) {
            int idx = tid + p * 256;                 // 0..2047
            int t = idx >> 10;                       // tile 0/1
            int r = (idx & 1023) >> 3, c = idx & 7;
            const char* addr = gb +
                ((size_t)(b * Tn + i0 + r) * Tn + j0a + t * 128) * 8 + (size_t)c * 128;
            asm volatile("prefetch.global.L2 [%0];" :: "l"(addr));
        }
    }

    // ---- load z tiles ----
    const uint4* zsrc = (const uint4*)g_zbf;
    #pragma unroll
    for (int p = 0; p < 8; p++) {
        int idx = tid + p * 256;
        int r = idx >> 4, c = idx & 15;
        uint32_t* dst = zi + r * SM_WSTRIDE + c * 4;
        *((uint4*)dst)                    = zsrc[(size_t)(b * Tn + i0 + r) * 16 + c];
        *((uint4*)(dst + TILE_WORDS))     = zsrc[(size_t)(b * Tn + j0a + r) * 16 + c];
        *((uint4*)(dst + 2 * TILE_WORDS)) = zsrc[(size_t)(b * Tn + j0b + r) * 16 + c];
    }
    if (tid < 128) {
        z2i_s[tid]  = g_z2[b * Tn + i0 + tid];
        z2j0_s[tid] = g_z2[b * Tn + j0a + tid];
    } else {
        z2j1_s[tid - 128] = g_z2[b * Tn + j0b + (tid - 128)];
    }
    __syncthreads();

    // ---- ldmatrix addressing ----
    const int wm = warp & 3, wn = warp >> 2;
    const int rowBase = wm * 32, colBase = wn * 64;
    const int gr = lane >> 2, q = lane & 3;

    const uint32_t ziB = smem_u32(zi);
    const int la = lane & 15, ha = lane >> 4;
    const uint32_t aAddr0 = ziB + (uint32_t)((rowBase + la) * SM_WSTRIDE + ha * 4) * 4;
    const uint32_t aAddr1 = aAddr0 + 16 * SM_WSTRIDE * 4;
    const int gq = lane >> 3;
    const uint32_t bOff = (uint32_t)((colBase + (gq >> 1) * 8 + (lane & 7)) * SM_WSTRIDE
                                     + (gq & 1) * 4) * 4;

    // sigma constants with log2e folded (exp(-k) = ex2(k * -log2e/..))
    const float sg0 = sigma[0], sg1 = sigma[1];
    const float cc0 = -1.44269504088896340736f / (2.0f * sg0 * sg0);
    const float cc1 = -1.44269504088896340736f / (2.0f * sg1 * sg1);
    ull CC; PACK2(CC, cc0, cc1);

    float acc[2][8][4];
    float total;

    // ---- tile 0 ----
    gram_mma(aAddr0, aAddr1, smem_u32(zj0) + bOff, acc);
    total = epi_tile(gt, b, i0, j0a, z2i_s, z2j0_s, rowBase, colBase, gr, q, acc, CC);

    // ---- tile 1 ----
    gram_mma(aAddr0, aAddr1, smem_u32(zj1) + bOff, acc);
    total += epi_tile(gt, b, i0, j0b, z2i_s, z2j1_s, rowBase, colBase, gr, q, acc, CC);

    // ---- block reduce -> per-CTA partial ----
    #pragma unroll
    for (int o = 16; o; o >>= 1) total += __shfl_xor_sync(0xffffffffu, total, o);
    __shared__ float wsum[8];
    if (lane == 0) wsum[warp] = total;
    __syncthreads();
    if (tid == 0) {
        float t = 0.f;
        #pragma unroll
        for (int w = 0; w < 8; w++) t += wsum[w];
        g_part[(b * 16 + it) * 8 + jt2] = (double)t;
    }
}

// ============================================================
// Kernel 3: deterministic final reduce (1024 partials)
// ============================================================
__global__ void reduce_kernel(float* __restrict__ out) {
    int tid = threadIdx.x;
    double s = 0.0;
    #pragma unroll
    for (int i = tid; i < Bn * 16 * 8; i += 256) s += g_part[i];
    __shared__ double sh[256];
    sh[tid] = s;
    __syncthreads();
    for (int o = 128; o; o >>= 1) {
        if (tid < o) sh[tid] += sh[tid + o];
        __syncthreads();
    }
    if (tid == 0)
        out[0] = (float)(sh[0] / ((double)Bn * (double)Tn * (double)Tn));
}

// ============================================================
extern "C" void kernel_launch(void* const* d_in, const int* in_sizes, int n_in,
                              void* d_out, int out_size) {
    const float *z = nullptr, *gt = nullptr, *sg = nullptr;
    for (int i = 0; i < n_in; i++) {
        if (in_sizes[i] == Bn * Tn * Dn)      z  = (const float*)d_in[i];
        else if (in_sizes[i] == 2)            sg = (const float*)d_in[i];
        else                                  gt = (const float*)d_in[i];
    }

    cudaFuncSetAttribute(main_kernel,
                         cudaFuncAttributeMaxDynamicSharedMemorySize, SMEM_BYTES);

    prep_kernel<<<Bn * Tn / 32, 256>>>(z);
    dim3 grid(8, 16, Bn);
    main_kernel<<<grid, 256, SMEM_BYTES>>>(gt, sg);
    reduce_kernel<<<1, 256>>>((float*)d_out);
}

// round 7
// speedup vs baseline: 1.3539x; 1.3539x over previous
#include <cuda_runtime.h>
#include <cuda_bf16.h>
#include <cstdint>
#include <cstddef>

#define Bn 8
#define Tn 2048
#define Dn 128
#define NCTA 304          // 2 CTAs x 152 SMs, persistent
#define NTILE 2048        // 8 * 16 * 16 tiles of 128x128

// ---- scratch (static device globals; no allocations) ----
__device__ __nv_bfloat16 g_zbf[Bn * Tn * Dn];   // 4 MB
__device__ float        g_z2[Bn * Tn];          // 64 KB
__device__ double       g_part[NCTA];           // per-CTA partials

__device__ __forceinline__ uint32_t smem_u32(const void* p) {
    uint32_t a;
    asm("{ .reg .u64 t; cvta.to.shared.u64 t, %1; cvt.u32.u64 %0, t; }"
        : "=r"(a) : "l"(p));
    return a;
}

#define LDSM_X4(r0, r1, r2, r3, a) \
    asm volatile("ldmatrix.sync.aligned.m8n8.x4.shared.b16 {%0,%1,%2,%3}, [%4];" \
                 : "=r"(r0), "=r"(r1), "=r"(r2), "=r"(r3) : "r"(a))

// ============================================================
// Kernel 1: bf16 cast of z + per-row squared norms (4 rows/warp)
// ============================================================
__global__ void __launch_bounds__(256) prep_kernel(const float* __restrict__ z) {
    const int warp = threadIdx.x >> 5, lane = threadIdx.x & 31;
    const int row0 = blockIdx.x * 32 + warp * 4;
    float4 v[4];
    #pragma unroll
    for (int r = 0; r < 4; r++)
        v[r] = ((const float4*)(z + (size_t)(row0 + r) * Dn))[lane];

    #pragma unroll
    for (int r = 0; r < 4; r++) {
        __nv_bfloat162 p0 = __floats2bfloat162_rn(v[r].x, v[r].y);
        __nv_bfloat162 p1 = __floats2bfloat162_rn(v[r].z, v[r].w);
        uint2 o;
        o.x = *reinterpret_cast<uint32_t*>(&p0);
        o.y = *reinterpret_cast<uint32_t*>(&p1);
        ((uint2*)g_zbf)[(size_t)(row0 + r) * 32 + lane] = o;
    }

    float s[4];
    #pragma unroll
    for (int r = 0; r < 4; r++)
        s[r] = v[r].x * v[r].x + v[r].y * v[r].y + v[r].z * v[r].z + v[r].w * v[r].w;
    #pragma unroll
    for (int off = 16; off; off >>= 1) {
        #pragma unroll
        for (int r = 0; r < 4; r++)
            s[r] += __shfl_xor_sync(0xffffffffu, s[r], off);
    }
    if (lane == 0) {
        #pragma unroll
        for (int r = 0; r < 4; r++) g_z2[row0 + r] = s[r];
    }
}

// ============================================================
// Kernel 2: persistent fused Gram(MMA) + w + weighted reduction
// grid = NCTA x 256 threads (8 warps, 4x2); tiles strided by NCTA
// ============================================================
#define SM_WSTRIDE 68
#define SMEM_BYTES (2 * 128 * SM_WSTRIDE * 4 + 2 * 128 * 4)

extern __shared__ unsigned char smem_raw[];

__device__ __forceinline__ void prefetch_tile(const char* gbase, int tile, int tid) {
    const int jt = tile & 15, it = (tile >> 4) & 15, b = tile >> 8;
    const int i0 = it * 128, j0 = jt * 128;
    #pragma unroll
    for (int p = 0; p < 4; p++) {
        int idx = tid + p * 256;                 // 0..1023
        int r = idx >> 3, c = idx & 7;
        const char* addr = gbase +
            ((size_t)(b * Tn + i0 + r) * Tn + j0) * 8 + (size_t)c * 128;
        asm volatile("prefetch.global.L2 [%0];" :: "l"(addr));
    }
}

__global__ void __launch_bounds__(256, 2)
main_kernel(const float* __restrict__ gt, const float* __restrict__ sigma) {
    uint32_t* zi  = (uint32_t*)smem_raw;
    uint32_t* zj  = zi + 128 * SM_WSTRIDE;
    float*    z2i = (float*)(zj + 128 * SM_WSTRIDE);
    float*    z2j = z2i + 128;
    __shared__ float wsum[8];

    const int tid = threadIdx.x;
    const int warp = tid >> 5, lane = tid & 31;

    // ---- constant ldmatrix addressing ----
    const int wm = warp & 3, wn = warp >> 2;     // 4 x 2 warp grid
    const int rowBase = wm * 32, colBase = wn * 64;
    const int gr = lane >> 2, q = lane & 3;
    const uint32_t ziB = smem_u32(zi), zjB = smem_u32(zj);
    const int la = lane & 15, ha = lane >> 4;
    const uint32_t aAddr0 = ziB + (uint32_t)((rowBase + la) * SM_WSTRIDE + ha * 4) * 4;
    const uint32_t aAddr1 = aAddr0 + 16 * SM_WSTRIDE * 4;
    const int gq = lane >> 3;
    const uint32_t bAddr = zjB + (uint32_t)((colBase + (gq >> 1) * 8 + (lane & 7)) * SM_WSTRIDE
                                            + (gq & 1) * 4) * 4;
    const uint32_t FN_STRIDE = 16 * SM_WSTRIDE * 4;

    const float sg0 = sigma[0], sg1 = sigma[1];
    const float c0 = 1.0f / (2.0f * sg0 * sg0), c1 = 1.0f / (2.0f * sg1 * sg1);
    const float4* gt4 = (const float4*)gt;
    const uint4* zsrc = (const uint4*)g_zbf;
    const char* gbase = (const char*)gt;

    double ctaAcc = 0.0;

    // warm-up prefetch for the first tile
    prefetch_tile(gbase, blockIdx.x, tid);

    for (int t = blockIdx.x; t < NTILE; t += NCTA) {
        const int jt = t & 15, it = (t >> 4) & 15, b = t >> 8;
        const int i0 = it * 128, j0 = jt * 128;

        // ---- load z tiles ----
        #pragma unroll
        for (int p = 0; p < 8; p++) {
            int idx = tid + p * 256;
            int r = idx >> 4, c = idx & 15;
            uint4 vi = zsrc[(size_t)(b * Tn + i0 + r) * 16 + c];
            *((uint4*)(zi + r * SM_WSTRIDE + c * 4)) = vi;
            uint4 vj = zsrc[(size_t)(b * Tn + j0 + r) * 16 + c];
            *((uint4*)(zj + r * SM_WSTRIDE + c * 4)) = vj;
        }
        if (tid < 128) z2i[tid] = g_z2[b * Tn + i0 + tid];
        else           z2j[tid - 128] = g_z2[b * Tn + j0 + (tid - 128)];
        __syncthreads();

        // ---- Gram via ldmatrix + mma.sync ----
        float acc[2][8][4];
        #pragma unroll
        for (int fm = 0; fm < 2; fm++)
            #pragma unroll
            for (int fn = 0; fn < 8; fn++)
                #pragma unroll
                for (int v = 0; v < 4; v++) acc[fm][fn][v] = 0.f;

        #pragma unroll
        for (int ks = 0; ks < 8; ks++) {
            const uint32_t ko = ks * 32;
            uint32_t a[2][4], bb[4][4];
            LDSM_X4(a[0][0], a[0][1], a[0][2], a[0][3], aAddr0 + ko);
            LDSM_X4(a[1][0], a[1][1], a[1][2], a[1][3], aAddr1 + ko);
            #pragma unroll
            for (int p = 0; p < 4; p++)
                LDSM_X4(bb[p][0], bb[p][1], bb[p][2], bb[p][3], bAddr + p * FN_STRIDE + ko);

            #pragma unroll
            for (int p = 0; p < 4; p++) {
                #pragma unroll
                for (int s = 0; s < 2; s++) {
                    const int fn = 2 * p + s;
                    const uint32_t b0 = bb[p][2 * s], b1 = bb[p][2 * s + 1];
                    #pragma unroll
                    for (int fm = 0; fm < 2; fm++) {
                        asm volatile(
                            "mma.sync.aligned.m16n8k16.row.col.f32.bf16.bf16.f32 "
                            "{%0,%1,%2,%3}, {%4,%5,%6,%7}, {%8,%9}, {%0,%1,%2,%3};"
                            : "+f"(acc[fm][fn][0]), "+f"(acc[fm][fn][1]),
                              "+f"(acc[fm][fn][2]), "+f"(acc[fm][fn][3])
                            : "r"(a[fm][0]), "r"(a[fm][1]), "r"(a[fm][2]), "r"(a[fm][3]),
                              "r"(b0), "r"(b1));
                    }
                }
            }
        }

        // ---- prefetch next tile's gt (overlaps this epilogue) ----
        const int tn = t + NCTA;
        if (tn < NTILE) prefetch_tile(gbase, tn, tid);

        // ---- epilogue: gt (L2-hot) -> w -> weighted accumulate ----
        float sum = 0.f;
        #pragma unroll
        for (int fm = 0; fm < 2; fm++) {
            const int ri = rowBase + fm * 16 + gr;
            const float z2a = z2i[ri];
            const float z2b = z2i[ri + 8];
            const size_t base0 = (size_t)(b * Tn + i0 + ri) * Tn + j0;
            const size_t base1 = base0 + (size_t)8 * Tn;
            #pragma unroll
            for (int fn = 0; fn < 8; fn++) {
                const int jj = colBase + fn * 8 + 2 * q;
                const float zj0 = z2j[jj], zj1 = z2j[jj + 1];
                const float4 gA = gt4[(base0 + jj) >> 1];
                const float4 gB = gt4[(base1 + jj) >> 1];
                const float w00 = __expf(-(gA.x * gA.x * c0 + gA.y * gA.y * c1));
                const float w01 = __expf(-(gA.z * gA.z * c0 + gA.w * gA.w * c1));
                const float w10 = __expf(-(gB.x * gB.x * c0 + gB.y * gB.y * c1));
                const float w11 = __expf(-(gB.z * gB.z * c0 + gB.w * gB.w * c1));
                sum += w00 * (z2a + zj0 - 2.f * acc[fm][fn][0]);
                sum += w01 * (z2a + zj1 - 2.f * acc[fm][fn][1]);
                sum += w10 * (z2b + zj0 - 2.f * acc[fm][fn][2]);
                sum += w11 * (z2b + zj1 - 2.f * acc[fm][fn][3]);
            }
        }

        // ---- block reduce this tile ----
        #pragma unroll
        for (int o = 16; o; o >>= 1) sum += __shfl_xor_sync(0xffffffffu, sum, o);
        if (lane == 0) wsum[warp] = sum;
        __syncthreads();
        if (tid == 0) {
            float tt = 0.f;
            #pragma unroll
            for (int w = 0; w < 8; w++) tt += wsum[w];
            ctaAcc += (double)tt;
        }
        __syncthreads();   // protect wsum + smem tiles before next iteration
    }

    if (tid == 0) g_part[blockIdx.x] = ctaAcc;
}

// ============================================================
// Kernel 3: deterministic final reduce (NCTA partials)
// ============================================================
__global__ void reduce_kernel(float* __restrict__ out) {
    int tid = threadIdx.x;
    double s = 0.0;
    for (int i = tid; i < NCTA; i += 256) s += g_part[i];
    __shared__ double sh[256];
    sh[tid] = s;
    __syncthreads();
    for (int o = 128; o; o >>= 1) {
        if (tid < o) sh[tid] += sh[tid + o];
        __syncthreads();
    }
    if (tid == 0)
        out[0] = (float)(sh[0] / ((double)Bn * (double)Tn * (double)Tn));
}

// ============================================================
extern "C" void kernel_launch(void* const* d_in, const int* in_sizes, int n_in,
                              void* d_out, int out_size) {
    const float *z = nullptr, *gt = nullptr, *sg = nullptr;
    for (int i = 0; i < n_in; i++) {
        if (in_sizes[i] == Bn * Tn * Dn)      z  = (const float*)d_in[i];
        else if (in_sizes[i] == 2)            sg = (const float*)d_in[i];
        else                                  gt = (const float*)d_in[i];
    }

    cudaFuncSetAttribute(main_kernel,
                         cudaFuncAttributeMaxDynamicSharedMemorySize, SMEM_BYTES);

    prep_kernel<<<Bn * Tn / 32, 256>>>(z);
    main_kernel<<<NCTA, 256, SMEM_BYTES>>>(gt, sg);
    reduce_kernel<<<1, 256>>>((float*)d_out);
}